// round 2
// baseline (speedup 1.0000x reference)
#include <cuda_runtime.h>

// CountVectorizer == per-row bincount over vocab followed by counts @ W + b.
// counts[b] has exactly SEQ non-zeros (with multiplicity), so
//   out[b, :] = bias + sum_t W[token_ids[b, t], :]
// == embedding gather-sum.
//
// Traffic: 204800 gathers x 512B = 105 MB through L2 (irreducible; no L1 reuse
// possible on a random 51 MB table), ~45 MB DRAM (unique rows; W mostly fits
// in L2). The binding cap is LTS throughput (~6300 B/cyc) -> floor ~9 us.
// R1 was latency-exposed (issue 28%, unroll 5, 32 regs). This version fully
// unrolls the 25 gathers per thread with a dual accumulator and a ~51-reg
// budget so ~8 LDG.128 stay in flight per thread.

#define CV_BATCH  1024
#define CV_SEQ    200
#define CV_D      128          // d_model
#define CV_D4     (CV_D / 4)   // 32 float4 per row
#define CV_GROUPS 8            // token groups per CTA (8 warps)
#define CV_TOK_PT (CV_SEQ / CV_GROUPS)   // 25 tokens per thread

__global__ __launch_bounds__(256, 5)
void count_vectorizer_kernel(const int* __restrict__ token_ids,
                             const float4* __restrict__ W4,
                             const float* __restrict__ bias,
                             float4* __restrict__ out4)
{
    __shared__ int s_ids[CV_SEQ];
    __shared__ float4 s_acc[CV_GROUPS][CV_D4];

    const int b = blockIdx.x;

    // Stage this row's 200 token ids (one coalesced load).
    if (threadIdx.x < CV_SEQ)
        s_ids[threadIdx.x] = token_ids[b * CV_SEQ + threadIdx.x];
    __syncthreads();

    const int lane = threadIdx.x & 31;   // which float4 of the 128-wide row
    const int grp  = threadIdx.x >> 5;   // token group 0..7 (= warp id)

    // Dual accumulator breaks the FADD RAW chain so load batches overlap.
    float4 acc[2];
    acc[0] = make_float4(0.f, 0.f, 0.f, 0.f);
    acc[1] = make_float4(0.f, 0.f, 0.f, 0.f);

    #pragma unroll
    for (int k = 0; k < CV_TOK_PT; k++) {
        // offset fits in 32-bit: id < 100000, *32 + lane < 3.2M
        const int off = s_ids[grp + CV_GROUPS * k] * CV_D4 + lane;
        const float4 v = __ldg(&W4[off]);
        float4& a = acc[k & 1];          // static after full unroll
        a.x += v.x; a.y += v.y; a.z += v.z; a.w += v.w;
    }

    float4 t;
    t.x = acc[0].x + acc[1].x;
    t.y = acc[0].y + acc[1].y;
    t.z = acc[0].z + acc[1].z;
    t.w = acc[0].w + acc[1].w;
    s_acc[grp][lane] = t;
    __syncthreads();

    // Warp 0 folds the 8 partials, adds bias, stores the row.
    if (grp == 0) {
        float4 a = s_acc[0][lane];
        #pragma unroll
        for (int g = 1; g < CV_GROUPS; g++) {
            const float4 v = s_acc[g][lane];
            a.x += v.x; a.y += v.y; a.z += v.z; a.w += v.w;
        }
        const float4 bb = reinterpret_cast<const float4*>(bias)[lane];
        a.x += bb.x; a.y += bb.y; a.z += bb.z; a.w += bb.w;
        out4[b * CV_D4 + lane] = a;
    }
}

extern "C" void kernel_launch(void* const* d_in, const int* in_sizes, int n_in,
                              void* d_out, int out_size)
{
    const int*   token_ids = (const int*)d_in[0];      // [1024, 200] int32
    const float* W         = (const float*)d_in[1];    // [100000, 128] f32
    const float* bias      = (const float*)d_in[2];    // [128] f32
    float*       out       = (float*)d_out;            // [1024, 128] f32

    (void)in_sizes; (void)n_in; (void)out_size;

    count_vectorizer_kernel<<<CV_BATCH, 256>>>(
        token_ids,
        reinterpret_cast<const float4*>(W),
        bias,
        reinterpret_cast<float4*>(out));
}

// round 5
// speedup vs baseline: 1.0103x; 1.0103x over previous
#include <cuda_runtime.h>
#include <cstdint>

// CountVectorizer == per-row bincount over vocab followed by counts @ W + b.
// counts[b] has exactly SEQ non-zeros (with multiplicity), so
//   out[b, :] = bias + sum_t W[token_ids[b, t], :]
// == embedding gather-sum.
//
// R1 (plain float4 gathers): 12.4 us = 45 MB DRAM / 3.4 TB/s -> the kernel is
// DRAM-bound on W refetch (W evicted between replays / during the pass).
// W = 51 MB fits in L2 (~100+ MB). sm_100 ptxas only accepts the
// L2::evict_last qualifier on 256-bit loads, so this version gathers W with
// ld.global.nc.L2::evict_last.v8.b32 (LDG.E.256): legal residency hint +
// half the LDG issue slots. Target: DRAM -> ~0 for W, wall moves to the
// irreducible 105 MB L2 gather traffic (~9 us).

#define CV_BATCH  1024
#define CV_SEQ    200
#define CV_D      128              // d_model (floats per row, 512 B)
#define CV_NG     16               // token groups per CTA
#define CV_NS     16               // 32-byte slices per row (16*32B = 512B)
#define CV_KFULL  (CV_SEQ / CV_NG) // 12 full rounds
#define CV_REM    (CV_SEQ - CV_KFULL * CV_NG) // 8 leftover tokens

__device__ __forceinline__ void ldg256_evict_last(const float* p, float* r)
{
    uint32_t u0,u1,u2,u3,u4,u5,u6,u7;
    asm volatile(
        "ld.global.nc.L2::evict_last.v8.b32 "
        "{%0,%1,%2,%3,%4,%5,%6,%7}, [%8];"
        : "=r"(u0),"=r"(u1),"=r"(u2),"=r"(u3),
          "=r"(u4),"=r"(u5),"=r"(u6),"=r"(u7)
        : "l"(p));
    r[0]=__uint_as_float(u0); r[1]=__uint_as_float(u1);
    r[2]=__uint_as_float(u2); r[3]=__uint_as_float(u3);
    r[4]=__uint_as_float(u4); r[5]=__uint_as_float(u5);
    r[6]=__uint_as_float(u6); r[7]=__uint_as_float(u7);
}

__global__ __launch_bounds__(256, 8)
void count_vectorizer_kernel(const int* __restrict__ token_ids,
                             const float* __restrict__ W,
                             const float* __restrict__ bias,
                             float* __restrict__ out)
{
    __shared__ int   s_ids[CV_SEQ];
    __shared__ float s_acc[CV_NG][CV_NS][8];   // 8 KB of partials

    const int b = blockIdx.x;

    if (threadIdx.x < CV_SEQ)
        s_ids[threadIdx.x] = token_ids[b * CV_SEQ + threadIdx.x];
    __syncthreads();

    const int slice = threadIdx.x & (CV_NS - 1);  // which 32B of the row
    const int grp   = threadIdx.x >> 4;           // token group 0..15

    float acc[8];
    #pragma unroll
    for (int i = 0; i < 8; i++) acc[i] = 0.f;

    float v[8];
    #pragma unroll
    for (int k = 0; k < CV_KFULL; k++) {
        const int tok = s_ids[grp + CV_NG * k];
        ldg256_evict_last(W + (tok * CV_D + slice * 8), v);
        #pragma unroll
        for (int i = 0; i < 8; i++) acc[i] += v[i];
    }
    // tokens 192..199 handled by groups 0..7
    if (grp < CV_REM) {
        const int tok = s_ids[CV_KFULL * CV_NG + grp];
        ldg256_evict_last(W + (tok * CV_D + slice * 8), v);
        #pragma unroll
        for (int i = 0; i < 8; i++) acc[i] += v[i];
    }

    #pragma unroll
    for (int i = 0; i < 8; i++) s_acc[grp][slice][i] = acc[i];
    __syncthreads();

    // 128 threads each fold one output float across the 16 group partials.
    if (threadIdx.x < CV_D) {
        const int d  = threadIdx.x;
        const int sl = d >> 3;
        const int ix = d & 7;
        float s = bias[d];
        #pragma unroll
        for (int g = 0; g < CV_NG; g++)
            s += s_acc[g][sl][ix];
        out[b * CV_D + d] = s;
    }
}

extern "C" void kernel_launch(void* const* d_in, const int* in_sizes, int n_in,
                              void* d_out, int out_size)
{
    const int*   token_ids = (const int*)d_in[0];      // [1024, 200] int32
    const float* W         = (const float*)d_in[1];    // [100000, 128] f32
    const float* bias      = (const float*)d_in[2];    // [128] f32
    float*       out       = (float*)d_out;            // [1024, 128] f32

    (void)in_sizes; (void)n_in; (void)out_size;

    count_vectorizer_kernel<<<CV_BATCH, 256>>>(token_ids, W, bias, out);
}

// round 6
// speedup vs baseline: 1.1073x; 1.0960x over previous
#include <cuda_runtime.h>

// CountVectorizer == per-row bincount over vocab followed by counts @ W + b.
//   out[b, :] = bias + sum_t W[token_ids[b, t], :]   (embedding gather-sum)
//
// Established (R1/R2/R5): timed loop is L2-warm (W resident across graph
// replays); three structurally different kernels all pin at 12.4-12.5 us =
// 105 MB of L2 gather delivery at ~8.5 TB/s, insensitive to occupancy/MLP/
// eviction policy -> at/near the path-independent LTS ceiling. Remaining
// slack is completion spread: grid=1024 is fully co-resident, so runtime =
// slowest CTA. This version halves the work quantum: grid 2048, each CTA =
// (batch row, d-half). 128 threads = 4 warps x 50 tokens, lane = float2
// slice of the 256B half-row. Disjoint outputs, no atomics, same total
// bytes; finer units let fast SMs absorb the spread.

#define CV_BATCH  1024
#define CV_SEQ    200
#define CV_D      128               // d_model
#define CV_D2     (CV_D / 2)        // 64 float2 per full row
#define CV_HALF2  32                // float2 per half row (256 B)
#define CV_WARPS  4
#define CV_TOKPW  (CV_SEQ / CV_WARPS)  // 50 tokens per warp

__global__ __launch_bounds__(128)
void count_vectorizer_kernel(const int* __restrict__ token_ids,
                             const float2* __restrict__ W2,
                             const float2* __restrict__ bias2,
                             float2* __restrict__ out2)
{
    __shared__ int    s_ids[CV_SEQ];
    __shared__ float2 s_acc[CV_WARPS][CV_HALF2];

    const int b = blockIdx.x >> 1;        // batch row
    const int h = blockIdx.x & 1;         // d-half (0: floats 0..63, 1: 64..127)

    // Stage this row's 200 token ids (2 coalesced rounds of 128).
    for (int i = threadIdx.x; i < CV_SEQ; i += 128)
        s_ids[i] = token_ids[b * CV_SEQ + i];
    __syncthreads();

    const int lane = threadIdx.x & 31;    // float2 slice within the half-row
    const int w    = threadIdx.x >> 5;    // warp id 0..3 (token stream)
    const int dcol = h * CV_HALF2 + lane; // float2 column in the full row

    float2 acc = make_float2(0.f, 0.f);

    // 50 gathers per warp; unroll 5 keeps ~5 LDG.64 (256B/warp) in flight.
    #pragma unroll 5
    for (int t = w; t < CV_SEQ; t += CV_WARPS) {
        const float2 v = __ldg(&W2[s_ids[t] * CV_D2 + dcol]);
        acc.x += v.x; acc.y += v.y;
    }

    s_acc[w][lane] = acc;
    __syncthreads();

    // Warp 0 folds the 4 partials, adds bias, stores the 256B half-row.
    if (w == 0) {
        float2 a = s_acc[0][lane];
        #pragma unroll
        for (int g = 1; g < CV_WARPS; g++) {
            const float2 v = s_acc[g][lane];
            a.x += v.x; a.y += v.y;
        }
        const float2 bb = __ldg(&bias2[dcol]);
        a.x += bb.x; a.y += bb.y;
        out2[b * CV_D2 + dcol] = a;
    }
}

extern "C" void kernel_launch(void* const* d_in, const int* in_sizes, int n_in,
                              void* d_out, int out_size)
{
    const int*   token_ids = (const int*)d_in[0];      // [1024, 200] int32
    const float* W         = (const float*)d_in[1];    // [100000, 128] f32
    const float* bias      = (const float*)d_in[2];    // [128] f32
    float*       out       = (float*)d_out;            // [1024, 128] f32

    (void)in_sizes; (void)n_in; (void)out_size;

    count_vectorizer_kernel<<<2 * CV_BATCH, 128>>>(
        token_ids,
        reinterpret_cast<const float2*>(W),
        reinterpret_cast<const float2*>(bias),
        reinterpret_cast<float2*>(out));
}